// round 7
// baseline (speedup 1.0000x reference)
#include <cuda_runtime.h>
#include <math.h>

// ---- problem constants ----
#define Vv    32000
#define Cc    768
#define Tt    1024
#define Bb    4
#define Hh    12
#define HSs   64
#define FFf   9216
#define NB    3
#define Mrows 4096            // B*T
#define LOGITS_N 131072000LL  // Mrows * Vv
#define ATT_SCALE 0.036084391824351615f  // 768^-0.5

// ---- scratch (device globals; no runtime allocation) ----
__device__ float g_x [Mrows*Cc];
__device__ float g_h [Mrows*Cc];
__device__ float g_q [Mrows*Cc];
__device__ float g_k [Mrows*Cc];
__device__ float g_v [Mrows*Cc];
__device__ float g_o [Mrows*Cc];
__device__ float g_ff[Mrows*FFf];
__device__ float g_wpack[NB*3*Cc*Cc];
__device__ float g_rowloss[Mrows];

// ============================================================
// pack wq/wk/wv: [blk][H][C][HS] -> [blk][mat][C][H*HS] row-major
// ============================================================
__global__ void pack_qkv_kernel(const float* __restrict__ wq,
                                const float* __restrict__ wk,
                                const float* __restrict__ wv) {
    int idx = blockIdx.x * blockDim.x + threadIdx.x;
    const int per = Cc * Cc;
    if (idx >= NB * 3 * per) return;
    int which = idx / per;      // 0..8
    int e     = idx % per;
    int blk = which / 3, mat = which % 3;
    int c = e / Cc, j = e % Cc;
    int h = j / HSs, d = j % HSs;
    const float* src = (mat == 0) ? wq : (mat == 1) ? wk : wv;
    g_wpack[(size_t)which * per + e] = src[(((size_t)blk*Hh + h)*Cc + c)*HSs + d];
}

// ============================================================
// embed: x[r,c] = tok_emb[sources[r], c] + pos_emb[r%T, c]
// ============================================================
__global__ void embed_kernel(const float* __restrict__ tok,
                             const float* __restrict__ pos,
                             const int* __restrict__ src) {
    int idx = blockIdx.x * blockDim.x + threadIdx.x;
    if (idx >= Mrows * Cc) return;
    int r = idx / Cc, c = idx % Cc;
    int t = r % Tt;
    g_x[idx] = tok[(size_t)src[r]*Cc + c] + pos[(size_t)t*Cc + c];
}

// ============================================================
// row LayerNorm: out = (x - mean)*rsqrt(var+eps)*g + b   (row = 768)
// grid = Mrows, block = 256
// ============================================================
__global__ void ln_kernel(const float* __restrict__ x,
                          const float* __restrict__ g,
                          const float* __restrict__ b,
                          float* __restrict__ out) {
    int r = blockIdx.x;
    int tid = threadIdx.x;
    const float* xr = x + (size_t)r * Cc;
    float vals[3];
    float s = 0.f, ss = 0.f;
#pragma unroll
    for (int i = 0; i < 3; i++) {
        float v = xr[tid + i*256];
        vals[i] = v; s += v; ss += v*v;
    }
#pragma unroll
    for (int o = 16; o; o >>= 1) {
        s  += __shfl_xor_sync(0xffffffffu, s,  o);
        ss += __shfl_xor_sync(0xffffffffu, ss, o);
    }
    __shared__ float sh_s[8], sh_ss[8];
    __shared__ float smean, srstd;
    int w = tid >> 5, l = tid & 31;
    if (l == 0) { sh_s[w] = s; sh_ss[w] = ss; }
    __syncthreads();
    if (tid == 0) {
        float S = 0.f, SS = 0.f;
        for (int i = 0; i < 8; i++) { S += sh_s[i]; SS += sh_ss[i]; }
        float m = S / Cc;
        float var = SS / Cc - m * m;
        smean = m; srstd = rsqrtf(var + 1e-5f);
    }
    __syncthreads();
    float m = smean, rstd = srstd;
#pragma unroll
    for (int i = 0; i < 3; i++) {
        int c = tid + i*256;
        out[(size_t)r*Cc + c] = (vals[i] - m) * rstd * g[c] + b[c];
    }
}

// ============================================================
// SGEMM: C = A[M,K] @ B[K,N] (+bias) (+relu / +residual)
// 128x128 tile, BK=16, 256 threads, 8x8 per thread.
// Requires M%128==0, N%128==0, K%16==0 (true for all shapes here).
// mode: 0 = bias+store, 1 = relu(bias+acc), 2 = res + acc + bias
// ============================================================
__global__ void __launch_bounds__(256)
sgemm_kernel(const float* __restrict__ A, const float* __restrict__ B,
             const float* __restrict__ bias, const float* __restrict__ res,
             float* __restrict__ C, int M, int N, int K, int mode) {
    __shared__ __align__(16) float As[16][128];   // transposed A tile
    __shared__ __align__(16) float Bs[16][128];
    int tid = threadIdx.x;
    int tr = tid >> 4, tc = tid & 15;
    int by = blockIdx.y, bx = blockIdx.x;
    const float* Ab  = A + (size_t)by * 128 * K;
    const float* Bb_ = B + (size_t)bx * 128;

    float acc[8][8];
#pragma unroll
    for (int i = 0; i < 8; i++)
#pragma unroll
        for (int j = 0; j < 8; j++) acc[i][j] = 0.f;

    int arow = tid >> 2;         // 0..63
    int akc  = (tid & 3) * 4;    // 0,4,8,12
    int bk   = tid >> 4;         // 0..15
    int bc   = (tid & 15) * 8;   // 0..120

    for (int k0 = 0; k0 < K; k0 += 16) {
#pragma unroll
        for (int it = 0; it < 2; it++) {
            int row = arow + it * 64;
            float4 av = *(const float4*)(Ab + (size_t)row * K + k0 + akc);
            As[akc+0][row] = av.x; As[akc+1][row] = av.y;
            As[akc+2][row] = av.z; As[akc+3][row] = av.w;
        }
        float4 bv0 = *(const float4*)(Bb_ + (size_t)(k0 + bk) * N + bc);
        float4 bv1 = *(const float4*)(Bb_ + (size_t)(k0 + bk) * N + bc + 4);
        *(float4*)&Bs[bk][bc]     = bv0;
        *(float4*)&Bs[bk][bc + 4] = bv1;
        __syncthreads();
#pragma unroll
        for (int k = 0; k < 16; k++) {
            float a[8], bfr[8];
            *(float4*)&a[0]   = *(const float4*)&As[k][tr*8];
            *(float4*)&a[4]   = *(const float4*)&As[k][tr*8 + 4];
            *(float4*)&bfr[0] = *(const float4*)&Bs[k][tc*8];
            *(float4*)&bfr[4] = *(const float4*)&Bs[k][tc*8 + 4];
#pragma unroll
            for (int i = 0; i < 8; i++)
#pragma unroll
                for (int j = 0; j < 8; j++)
                    acc[i][j] += a[i] * bfr[j];
        }
        __syncthreads();
    }

    int row0 = by*128 + tr*8, col0 = bx*128 + tc*8;
#pragma unroll
    for (int i = 0; i < 8; i++) {
#pragma unroll
        for (int j = 0; j < 8; j++) {
            float v = acc[i][j];
            if (bias) v += bias[col0 + j];
            if (mode == 1) v = fmaxf(v, 0.f);
            else if (mode == 2) v += res[(size_t)(row0 + i) * N + col0 + j];
            C[(size_t)(row0 + i) * N + col0 + j] = v;
        }
    }
}

// ============================================================
// fused causal attention, fp32, online softmax.
// q/k/v/o layout: [B, T, C] with head h occupying cols [h*64, h*64+64)
// grid = (B*H, T/64), block = 256.
// ============================================================
__global__ void __launch_bounds__(256)
attn_kernel(const float* __restrict__ Q, const float* __restrict__ K,
            const float* __restrict__ V, float* __restrict__ O) {
    int bh = blockIdx.x;
    int b = bh / Hh, h = bh % Hh;
    int qt0 = blockIdx.y * 64;
    int tid = threadIdx.x;

    __shared__ float Qs[64][64];
    __shared__ float Ks[32][65];
    __shared__ float Vs[32][65];
    __shared__ float Ps[64][33];
    __shared__ float mrow[64], lrow[64], arow_s[64];

    // load Q tile (coalesced)
#pragma unroll
    for (int i = 0; i < 16; i++) {
        int e = tid + i*256;
        int r = e >> 6, d = e & 63;
        Qs[r][d] = Q[((size_t)(b*Tt + qt0 + r))*Cc + h*64 + d];
    }
    if (tid < 64) { mrow[tid] = -1e30f; lrow[tid] = 0.f; }

    float o[16];
#pragma unroll
    for (int i = 0; i < 16; i++) o[i] = 0.f;

    int d_o  = tid & 63;   // O column
    int rg_o = tid >> 6;   // O row group (x16)
    int s_s  = tid & 31;   // S column
    int rg_s = tid >> 5;   // S row group (x8)

    int nkt = (qt0 + 64) / 32;
    for (int kt = 0; kt < nkt; kt++) {
        __syncthreads();
        // load K/V tiles (32x64 each)
#pragma unroll
        for (int i = 0; i < 8; i++) {
            int e = tid + i*256;
            int s = e >> 6, d = e & 63;
            size_t gi = ((size_t)(b*Tt + kt*32 + s))*Cc + h*64 + d;
            Ks[s][d] = K[gi];
            Vs[s][d] = V[gi];
        }
        __syncthreads();
        // S = Q K^T * scale (+ causal mask)
#pragma unroll
        for (int i = 0; i < 8; i++) {
            int r = rg_s*8 + i;
            float a = 0.f;
#pragma unroll
            for (int k = 0; k < 64; k++) a += Qs[r][k] * Ks[s_s][k];
            int sg = kt*32 + s_s, tg = qt0 + r;
            Ps[r][s_s] = (sg <= tg) ? a * ATT_SCALE : -1e30f;
        }
        __syncthreads();
        // online softmax stats (one thread per row)
        if (tid < 64) {
            int r = tid;
            float m_old = mrow[r];
            float mx = m_old;
#pragma unroll
            for (int s = 0; s < 32; s++) mx = fmaxf(mx, Ps[r][s]);
            float alpha = expf(m_old - mx);
            float sum = 0.f;
#pragma unroll
            for (int s = 0; s < 32; s++) {
                float p = expf(Ps[r][s] - mx);
                Ps[r][s] = p; sum += p;
            }
            mrow[r] = mx;
            lrow[r] = lrow[r] * alpha + sum;
            arow_s[r] = alpha;
        }
        __syncthreads();
        // O = O*alpha + P V
#pragma unroll
        for (int i = 0; i < 16; i++) {
            int r = rg_o*16 + i;
            float al = arow_s[r];
            float a = 0.f;
#pragma unroll
            for (int s = 0; s < 32; s++) a += Ps[r][s] * Vs[s][d_o];
            o[i] = o[i] * al + a;
        }
    }
    // write normalized output
#pragma unroll
    for (int i = 0; i < 16; i++) {
        int r = rg_o*16 + i;
        O[((size_t)(b*Tt + qt0 + r))*Cc + h*64 + d_o] = o[i] / lrow[r];
    }
}

// ============================================================
// loss: per-row log-softmax NLL, then mean
// ============================================================
__global__ void loss_rows_kernel(const float* __restrict__ logits,
                                 const int* __restrict__ targets) {
    int r = blockIdx.x, tid = threadIdx.x;
    const float* row = logits + (size_t)r * Vv;
    __shared__ float sh[8];
    __shared__ float bmax;
    float mx = -1e30f;
    for (int c = tid; c < Vv; c += 256) mx = fmaxf(mx, row[c]);
#pragma unroll
    for (int o = 16; o; o >>= 1) mx = fmaxf(mx, __shfl_xor_sync(0xffffffffu, mx, o));
    if ((tid & 31) == 0) sh[tid >> 5] = mx;
    __syncthreads();
    if (tid == 0) {
        float m = sh[0];
        for (int i = 1; i < 8; i++) m = fmaxf(m, sh[i]);
        bmax = m;
    }
    __syncthreads();
    mx = bmax;
    float s = 0.f;
    for (int c = tid; c < Vv; c += 256) s += expf(row[c] - mx);
#pragma unroll
    for (int o = 16; o; o >>= 1) s += __shfl_xor_sync(0xffffffffu, s, o);
    if ((tid & 31) == 0) sh[tid >> 5] = s;
    __syncthreads();
    if (tid == 0) {
        float S = 0.f;
        for (int i = 0; i < 8; i++) S += sh[i];
        g_rowloss[r] = mx + logf(S) - row[targets[r]];
    }
}

__global__ void loss_reduce_kernel(float* __restrict__ d_out, long long out_size) {
    int tid = threadIdx.x;
    __shared__ float sh[8];
    float s = 0.f;
    for (int i = tid; i < Mrows; i += 256) s += g_rowloss[i];
#pragma unroll
    for (int o = 16; o; o >>= 1) s += __shfl_xor_sync(0xffffffffu, s, o);
    if ((tid & 31) == 0) sh[tid >> 5] = s;
    __syncthreads();
    if (tid == 0) {
        float S = 0.f;
        for (int i = 0; i < 8; i++) S += sh[i];
        float loss = S / (float)Mrows;
        for (long long i = LOGITS_N; i < out_size; i++) d_out[i] = loss;
    }
}

// ============================================================
// host orchestration
// ============================================================
extern "C" void kernel_launch(void* const* d_in, const int* in_sizes, int n_in,
                              void* d_out, int out_size) {
    const float* tok_emb = (const float*)d_in[0];
    const float* pos_emb = (const float*)d_in[1];
    const float* wq      = (const float*)d_in[2];
    const float* wk      = (const float*)d_in[3];
    const float* wv      = (const float*)d_in[4];
    const float* wproj   = (const float*)d_in[5];
    const float* bproj   = (const float*)d_in[6];
    const float* g1      = (const float*)d_in[7];
    const float* b1      = (const float*)d_in[8];
    const float* g2      = (const float*)d_in[9];
    const float* b2      = (const float*)d_in[10];
    const float* wf1     = (const float*)d_in[11];
    const float* bf1     = (const float*)d_in[12];
    const float* wf2     = (const float*)d_in[13];
    const float* bf2     = (const float*)d_in[14];
    const float* gf      = (const float*)d_in[15];
    const float* bfv     = (const float*)d_in[16];
    const float* wlm     = (const float*)d_in[17];
    const float* blm     = (const float*)d_in[18];
    const int*   sources = (const int*)d_in[19];
    const int*   targets = (const int*)d_in[20];
    float* out = (float*)d_out;

    float *px, *ph, *pq, *pk, *pv, *po, *pff, *pwp;
    cudaGetSymbolAddress((void**)&px,  g_x);
    cudaGetSymbolAddress((void**)&ph,  g_h);
    cudaGetSymbolAddress((void**)&pq,  g_q);
    cudaGetSymbolAddress((void**)&pk,  g_k);
    cudaGetSymbolAddress((void**)&pv,  g_v);
    cudaGetSymbolAddress((void**)&po,  g_o);
    cudaGetSymbolAddress((void**)&pff, g_ff);
    cudaGetSymbolAddress((void**)&pwp, g_wpack);

    pack_qkv_kernel<<<(NB*3*Cc*Cc + 255)/256, 256>>>(wq, wk, wv);
    embed_kernel<<<(Mrows*Cc + 255)/256, 256>>>(tok_emb, pos_emb, sources);

    dim3 gcc(Cc/128, Mrows/128);      // 768-wide GEMMs
    dim3 gff(FFf/128, Mrows/128);     // FF1
    dim3 glm(Vv/128, Mrows/128);      // LM head

    for (int i = 0; i < NB; i++) {
        ln_kernel<<<Mrows, 256>>>(px, g1 + i*Cc, b1 + i*Cc, ph);

        sgemm_kernel<<<gcc, 256>>>(ph, pwp + (size_t)(i*3+0)*Cc*Cc, nullptr, nullptr,
                                   pq, Mrows, Cc, Cc, 0);
        sgemm_kernel<<<gcc, 256>>>(ph, pwp + (size_t)(i*3+1)*Cc*Cc, nullptr, nullptr,
                                   pk, Mrows, Cc, Cc, 0);
        sgemm_kernel<<<gcc, 256>>>(ph, pwp + (size_t)(i*3+2)*Cc*Cc, nullptr, nullptr,
                                   pv, Mrows, Cc, Cc, 0);

        attn_kernel<<<dim3(Bb*Hh, Tt/64), 256>>>(pq, pk, pv, po);

        sgemm_kernel<<<gcc, 256>>>(po, wproj + (size_t)i*Cc*Cc, bproj + i*Cc, px,
                                   px, Mrows, Cc, Cc, 2);

        ln_kernel<<<Mrows, 256>>>(px, g2 + i*Cc, b2 + i*Cc, ph);

        sgemm_kernel<<<gff, 256>>>(ph, wf1 + (size_t)i*Cc*FFf, bf1 + i*FFf, nullptr,
                                   pff, Mrows, FFf, Cc, 1);
        sgemm_kernel<<<gcc, 256>>>(pff, wf2 + (size_t)i*FFf*Cc, bf2 + i*Cc, px,
                                   px, Mrows, Cc, FFf, 2);
    }

    ln_kernel<<<Mrows, 256>>>(px, gf, bfv, ph);
    sgemm_kernel<<<glm, 256>>>(ph, wlm, blm, nullptr, out, Mrows, Vv, Cc, 0);

    loss_rows_kernel<<<Mrows, 256>>>(out, targets);
    loss_reduce_kernel<<<1, 256>>>(out, (long long)out_size);
}

// round 10
// speedup vs baseline: 1.5812x; 1.5812x over previous
#include <cuda_runtime.h>
#include <cuda_bf16.h>
#include <math.h>
#include <stdint.h>

#define Vv    32000
#define Cc    768
#define Tt    1024
#define Hh    12
#define FFf   9216
#define NB    3
#define Mrows 4096
#define QKVN  2304
#define NBATCH 4
#define LOGITS_N 131072000LL
#define ATT_SCALE 0.036084391824351615f

typedef __nv_bfloat16 bf16;

// ---- scratch (device globals; no runtime allocation) ----
__device__ float g_x   [Mrows*Cc];
__device__ float g_qkv [Mrows*QKVN];
__device__ __align__(128) bf16 g_asp [(size_t)Mrows*2304];        // split activations [M, 3*768] = [hi|lo|hi]
__device__ __align__(128) bf16 g_ffsp[(size_t)Mrows*27648];       // split FF activations [M, 3*9216]
__device__ float g_rowloss[Mrows];
// split, transposed weights: [N, 3K] bf16, K-major, [hi | hi | lo]
__device__ __align__(128) bf16 g_wqkvB [(size_t)NB*2304*2304];
__device__ __align__(128) bf16 g_wprojB[(size_t)NB*768*2304];
__device__ __align__(128) bf16 g_wf1B  [(size_t)NB*9216*2304];
__device__ __align__(128) bf16 g_wf2B  [(size_t)NB*768*27648];
__device__ __align__(128) bf16 g_wlmB  [(size_t)Vv*2304];

// ================= PTX helpers (arch-portable, sm_80+) =================
__device__ __forceinline__ uint32_t smem_u32(const void* p) {
    uint32_t a;
    asm("{ .reg .u64 t; cvta.to.shared.u64 t, %1; cvt.u32.u64 %0, t; }" : "=r"(a) : "l"(p));
    return a;
}
#define CP16(dst, src)  asm volatile("cp.async.cg.shared.global [%0], [%1], 16;" :: "r"(dst), "l"(src))
#define CP_COMMIT()     asm volatile("cp.async.commit_group;" ::: "memory")
#define CP_WAITG(n)     asm volatile("cp.async.wait_group %0;" :: "n"(n) : "memory")

__device__ __forceinline__ void ldm_x4(uint32_t* r, uint32_t addr) {
    asm volatile("ldmatrix.sync.aligned.m8n8.x4.shared.b16 {%0,%1,%2,%3}, [%4];"
        : "=r"(r[0]), "=r"(r[1]), "=r"(r[2]), "=r"(r[3]) : "r"(addr));
}
__device__ __forceinline__ void mma16816(float* c, const uint32_t* a, const uint32_t* b) {
    asm volatile("mma.sync.aligned.m16n8k16.row.col.f32.bf16.bf16.f32 "
        "{%0,%1,%2,%3}, {%4,%5,%6,%7}, {%8,%9}, {%0,%1,%2,%3};"
        : "+f"(c[0]), "+f"(c[1]), "+f"(c[2]), "+f"(c[3])
        : "r"(a[0]), "r"(a[1]), "r"(a[2]), "r"(a[3]), "r"(b[0]), "r"(b[1]));
}

__device__ __forceinline__ void split_store(bf16* p, size_t o, size_t K, float v) {
    bf16 h = __float2bfloat16(v);
    bf16 l = __float2bfloat16(v - __bfloat162float(h));
    p[o] = h; p[o + K] = l; p[o + 2*K] = h;   // A layout: [hi | lo | hi]
}

// ================= HMMA GEMM =================
// C[M,N] = A'[M,K3] @ B'[N,K3]^T  (bf16, fp32 accum)
// Tile 128x128, BK=32, 256 threads, 8 warps (4 m x 2 n), warp tile 32x64.
// MODE 0: outF = acc (+bias)        MODE 1: relu(acc+bias) -> split bf16 outS
// MODE 2: outF = acc + bias + res
#define SSTR 40   // smem row stride in bf16 (80B): conflict-free ldmatrix
template<int MODE>
__global__ void __launch_bounds__(256, 1)
hmma_gemm(const bf16* __restrict__ A, const bf16* __restrict__ Bw,
          const float* __restrict__ bias, const float* __restrict__ res,
          float* __restrict__ outF, bf16* __restrict__ outS,
          int K3, int N, int KoutS)
{
    __shared__ __align__(16) bf16 As[2][128 * SSTR];
    __shared__ __align__(16) bf16 Bs[2][128 * SSTR];

    int tid = threadIdx.x, lane = tid & 31, wid = tid >> 5;
    int warp_m = wid & 3, warp_n = wid >> 2;       // 4 x 2 warps
    int gm = blockIdx.x, gn = blockIdx.y;

    const bf16* Aptr = A  + (size_t)(gm * 128) * K3;
    const bf16* Bptr = Bw + (size_t)(gn * 128) * K3;

    float acc[2][8][4];
#pragma unroll
    for (int i = 0; i < 2; i++)
#pragma unroll
        for (int j = 0; j < 8; j++)
#pragma unroll
            for (int q = 0; q < 4; q++) acc[i][j][q] = 0.f;

    int r0 = tid >> 2, sub = (tid & 3) * 8;        // cp.async row / elem-offset

    auto load_tiles = [&](int stage, int k0) {
        uint32_t sa = smem_u32(&As[stage][0]);
        uint32_t sb = smem_u32(&Bs[stage][0]);
#pragma unroll
        for (int hf = 0; hf < 2; hf++) {
            int row = r0 + hf * 64;
            CP16(sa + (row * SSTR + sub) * 2, Aptr + (size_t)row * K3 + k0 + sub);
            CP16(sb + (row * SSTR + sub) * 2, Bptr + (size_t)row * K3 + k0 + sub);
        }
        CP_COMMIT();
    };

    int NK = K3 / 32;
    load_tiles(0, 0);

    for (int it = 0; it < NK; it++) {
        if (it + 1 < NK) { load_tiles((it + 1) & 1, (it + 1) * 32); CP_WAITG(1); }
        else             { CP_WAITG(0); }
        __syncthreads();

        int st = it & 1;
        uint32_t abase = smem_u32(&As[st][0]);
        uint32_t bbase = smem_u32(&Bs[st][0]);
#pragma unroll
        for (int kk = 0; kk < 32; kk += 16) {
            uint32_t af[2][4], bfr[4][4];
#pragma unroll
            for (int mt = 0; mt < 2; mt++) {
                int row = warp_m * 32 + mt * 16 + (lane & 15);
                int col = kk + (lane >> 4) * 8;
                ldm_x4(af[mt], abase + (row * SSTR + col) * 2);
            }
#pragma unroll
            for (int bt = 0; bt < 4; bt++) {
                int row = warp_n * 64 + bt * 16 + (lane & 15);
                int col = kk + (lane >> 4) * 8;
                ldm_x4(bfr[bt], bbase + (row * SSTR + col) * 2);
            }
#pragma unroll
            for (int mt = 0; mt < 2; mt++)
#pragma unroll
                for (int bt = 0; bt < 4; bt++) {
                    uint32_t blo[2] = { bfr[bt][0], bfr[bt][2] };  // n = bt*16+0..7
                    uint32_t bhi[2] = { bfr[bt][1], bfr[bt][3] };  // n = bt*16+8..15
                    mma16816(acc[mt][bt * 2 + 0], af[mt], blo);
                    mma16816(acc[mt][bt * 2 + 1], af[mt], bhi);
                }
        }
        __syncthreads();
    }

    // epilogue: c fragment rows lane>>2 (+8), cols (lane&3)*2 (+1)
    int rbase = gm * 128 + warp_m * 32;
    int cbase = gn * 128 + warp_n * 64;
#pragma unroll
    for (int mt = 0; mt < 2; mt++) {
#pragma unroll
        for (int nt = 0; nt < 8; nt++) {
#pragma unroll
            for (int hf = 0; hf < 2; hf++) {
                int grow = rbase + mt * 16 + (lane >> 2) + hf * 8;
                int gcol = cbase + nt * 8 + (lane & 3) * 2;
                float v0 = acc[mt][nt][hf * 2 + 0];
                float v1 = acc[mt][nt][hf * 2 + 1];
                if (bias) { v0 += bias[gcol]; v1 += bias[gcol + 1]; }
                if (MODE == 2) {
                    const float* rr = res + (size_t)grow * N + gcol;
                    v0 += rr[0]; v1 += rr[1];
                }
                if (MODE == 1) {
                    v0 = fmaxf(v0, 0.f); v1 = fmaxf(v1, 0.f);
                    size_t o = (size_t)grow * (3 * (size_t)KoutS) + gcol;
                    split_store(outS, o,     KoutS, v0);
                    split_store(outS, o + 1, KoutS, v1);
                } else {
                    float* po = outF + (size_t)grow * N + gcol;
                    po[0] = v0; po[1] = v1;
                }
            }
        }
    }
}

// ================= weight packing =================
// src [K,N] fp32 -> dst [N,3K] bf16 K-major: [hi | hi | lo]
__global__ void tsplit_kernel(const float* __restrict__ src, bf16* __restrict__ dst,
                              int K, int N) {
    __shared__ float t[32][33];
    int n0 = blockIdx.x * 32, k0 = blockIdx.y * 32;
    int tx = threadIdx.x, ty = threadIdx.y;
#pragma unroll
    for (int i = 0; i < 32; i += 8) t[ty + i][tx] = src[(size_t)(k0 + ty + i) * N + n0 + tx];
    __syncthreads();
#pragma unroll
    for (int i = 0; i < 32; i += 8) {
        float v = t[tx][ty + i];
        int n = n0 + ty + i, k = k0 + tx;
        bf16 h = __float2bfloat16(v);
        bf16 l = __float2bfloat16(v - __bfloat162float(h));
        size_t o = (size_t)n * (3 * (size_t)K) + k;
        dst[o] = h; dst[o + K] = h; dst[o + 2 * K] = l;
    }
}

// wq/wk/wv [blk][H][768][64] -> g_wqkvB [blk][N=2304][3K=2304]
__global__ void qkvpack_kernel(const float* __restrict__ wq, const float* __restrict__ wk,
                               const float* __restrict__ wv) {
    __shared__ float t[32][33];
    int z = blockIdx.z;
    int blk = z / 36, rem = z % 36, mat = rem / 12, h = rem % 12;
    const float* src = (mat == 0 ? wq : mat == 1 ? wk : wv) + (size_t)(blk * 12 + h) * 768 * 64;
    int d0 = blockIdx.x * 32, c0 = blockIdx.y * 32;
    int tx = threadIdx.x, ty = threadIdx.y;
#pragma unroll
    for (int i = 0; i < 32; i += 8) t[ty + i][tx] = src[(size_t)(c0 + ty + i) * 64 + d0 + tx];
    __syncthreads();
    bf16* dst = g_wqkvB + (size_t)blk * 2304 * 2304;
#pragma unroll
    for (int i = 0; i < 32; i += 8) {
        float v = t[tx][ty + i];
        int n = mat * 768 + h * 64 + d0 + ty + i;
        int c = c0 + tx;
        bf16 hh = __float2bfloat16(v);
        bf16 ll = __float2bfloat16(v - __bfloat162float(hh));
        size_t o = (size_t)n * 2304 + c;
        dst[o] = hh; dst[o + 768] = hh; dst[o + 1536] = ll;
    }
}

// ================= embed =================
__global__ void embed_kernel(const float* __restrict__ tok, const float* __restrict__ pos,
                             const int* __restrict__ src) {
    int idx = blockIdx.x * blockDim.x + threadIdx.x;
    if (idx >= Mrows * Cc) return;
    int r = idx / Cc, c = idx % Cc;
    g_x[idx] = tok[(size_t)src[r] * Cc + c] + pos[(size_t)(r % Tt) * Cc + c];
}

// ================= LayerNorm -> split bf16 =================
__global__ void ln_kernel(const float* __restrict__ x, const float* __restrict__ g,
                          const float* __restrict__ b) {
    int r = blockIdx.x, tid = threadIdx.x;
    const float* xr = x + (size_t)r * Cc;
    float vals[3];
    float s = 0.f, ss = 0.f;
#pragma unroll
    for (int i = 0; i < 3; i++) {
        float v = xr[tid + i * 256];
        vals[i] = v; s += v; ss += v * v;
    }
#pragma unroll
    for (int o = 16; o; o >>= 1) {
        s  += __shfl_xor_sync(0xffffffffu, s,  o);
        ss += __shfl_xor_sync(0xffffffffu, ss, o);
    }
    __shared__ float sh_s[8], sh_ss[8], smean, srstd;
    int w = tid >> 5, l = tid & 31;
    if (l == 0) { sh_s[w] = s; sh_ss[w] = ss; }
    __syncthreads();
    if (tid == 0) {
        float S = 0.f, SS = 0.f;
        for (int i = 0; i < 8; i++) { S += sh_s[i]; SS += sh_ss[i]; }
        float m = S / Cc;
        smean = m; srstd = rsqrtf(SS / Cc - m * m + 1e-5f);
    }
    __syncthreads();
    float m = smean, rstd = srstd;
#pragma unroll
    for (int i = 0; i < 3; i++) {
        int c = tid + i * 256;
        float y = (vals[i] - m) * rstd * g[c] + b[c];
        split_store(g_asp, (size_t)r * 2304 + c, 768, y);
    }
}

// ================= causal attention (fp32), split output =================
__global__ void __launch_bounds__(256)
attn_kernel(const float* __restrict__ QKV) {
    int bh = blockIdx.x;
    int b = bh / Hh, h = bh % Hh;
    int qt0 = blockIdx.y * 64;
    int tid = threadIdx.x;

    __shared__ float Qs[64][64];
    __shared__ float Ks[32][65];
    __shared__ float Vs[32][65];
    __shared__ float Ps[64][33];
    __shared__ float mrow[64], lrow[64], arow_s[64];

#pragma unroll
    for (int i = 0; i < 16; i++) {
        int e = tid + i * 256;
        int r = e >> 6, d = e & 63;
        Qs[r][d] = QKV[((size_t)(b * Tt + qt0 + r)) * QKVN + h * 64 + d];
    }
    if (tid < 64) { mrow[tid] = -1e30f; lrow[tid] = 0.f; }

    float o[16];
#pragma unroll
    for (int i = 0; i < 16; i++) o[i] = 0.f;

    int d_o = tid & 63, rg_o = tid >> 6;
    int s_s = tid & 31, rg_s = tid >> 5;

    int nkt = (qt0 + 64) / 32;
    for (int kt = 0; kt < nkt; kt++) {
        __syncthreads();
#pragma unroll
        for (int i = 0; i < 8; i++) {
            int e = tid + i * 256;
            int s = e >> 6, d = e & 63;
            size_t gi = ((size_t)(b * Tt + kt * 32 + s)) * QKVN + h * 64 + d;
            Ks[s][d] = QKV[gi + 768];
            Vs[s][d] = QKV[gi + 1536];
        }
        __syncthreads();
#pragma unroll
        for (int i = 0; i < 8; i++) {
            int r = rg_s * 8 + i;
            float a = 0.f;
#pragma unroll
            for (int k = 0; k < 64; k++) a += Qs[r][k] * Ks[s_s][k];
            int sg = kt * 32 + s_s, tg = qt0 + r;
            Ps[r][s_s] = (sg <= tg) ? a * ATT_SCALE : -1e30f;
        }
        __syncthreads();
        if (tid < 64) {
            int r = tid;
            float m_old = mrow[r], mx = m_old;
#pragma unroll
            for (int s = 0; s < 32; s++) mx = fmaxf(mx, Ps[r][s]);
            float alpha = expf(m_old - mx), sum = 0.f;
#pragma unroll
            for (int s = 0; s < 32; s++) { float p = expf(Ps[r][s] - mx); Ps[r][s] = p; sum += p; }
            mrow[r] = mx; lrow[r] = lrow[r] * alpha + sum; arow_s[r] = alpha;
        }
        __syncthreads();
#pragma unroll
        for (int i = 0; i < 16; i++) {
            int r = rg_o * 16 + i;
            float al = arow_s[r], a = 0.f;
#pragma unroll
            for (int s = 0; s < 32; s++) a += Ps[r][s] * Vs[s][d_o];
            o[i] = o[i] * al + a;
        }
    }
#pragma unroll
    for (int i = 0; i < 16; i++) {
        int r = rg_o * 16 + i;
        float v = o[i] / lrow[r];
        split_store(g_asp, ((size_t)(b * Tt + qt0 + r)) * 2304 + h * 64 + d_o, 768, v);
    }
}

// ================= loss =================
__global__ void loss_rows_kernel(const float* __restrict__ logits, const int* __restrict__ targets) {
    int r = blockIdx.x, tid = threadIdx.x;
    const float* row = logits + (size_t)r * Vv;
    __shared__ float sh[8];
    __shared__ float bmax;
    float mx = -1e30f;
    for (int c = tid; c < Vv; c += 256) mx = fmaxf(mx, row[c]);
#pragma unroll
    for (int o = 16; o; o >>= 1) mx = fmaxf(mx, __shfl_xor_sync(0xffffffffu, mx, o));
    if ((tid & 31) == 0) sh[tid >> 5] = mx;
    __syncthreads();
    if (tid == 0) {
        float m = sh[0];
        for (int i = 1; i < 8; i++) m = fmaxf(m, sh[i]);
        bmax = m;
    }
    __syncthreads();
    mx = bmax;
    float s = 0.f;
    for (int c = tid; c < Vv; c += 256) s += expf(row[c] - mx);
#pragma unroll
    for (int o = 16; o; o >>= 1) s += __shfl_xor_sync(0xffffffffu, s, o);
    if ((tid & 31) == 0) sh[tid >> 5] = s;
    __syncthreads();
    if (tid == 0) {
        float S = 0.f;
        for (int i = 0; i < 8; i++) S += sh[i];
        g_rowloss[r] = mx + logf(S) - row[targets[r]];
    }
}

__global__ void loss_reduce_kernel(float* __restrict__ d_out, long long out_size) {
    int tid = threadIdx.x;
    __shared__ float sh[8];
    float s = 0.f;
    for (int i = tid; i < Mrows; i += 256) s += g_rowloss[i];
#pragma unroll
    for (int o = 16; o; o >>= 1) s += __shfl_xor_sync(0xffffffffu, s, o);
    if ((tid & 31) == 0) sh[tid >> 5] = s;
    __syncthreads();
    if (tid == 0) {
        float S = 0.f;
        for (int i = 0; i < 8; i++) S += sh[i];
        float loss = S / (float)Mrows;
        for (long long i = LOGITS_N; i < out_size; i++) d_out[i] = loss;
    }
}

// ================= host orchestration =================
extern "C" void kernel_launch(void* const* d_in, const int* in_sizes, int n_in,
                              void* d_out, int out_size) {
    const float* tok_emb = (const float*)d_in[0];
    const float* pos_emb = (const float*)d_in[1];
    const float* wq      = (const float*)d_in[2];
    const float* wk      = (const float*)d_in[3];
    const float* wv      = (const float*)d_in[4];
    const float* wproj   = (const float*)d_in[5];
    const float* bproj   = (const float*)d_in[6];
    const float* g1      = (const float*)d_in[7];
    const float* b1      = (const float*)d_in[8];
    const float* g2      = (const float*)d_in[9];
    const float* b2      = (const float*)d_in[10];
    const float* wf1     = (const float*)d_in[11];
    const float* bf1     = (const float*)d_in[12];
    const float* wf2     = (const float*)d_in[13];
    const float* bf2     = (const float*)d_in[14];
    const float* gf      = (const float*)d_in[15];
    const float* bfv     = (const float*)d_in[16];
    const float* wlm     = (const float*)d_in[17];
    const float* blm     = (const float*)d_in[18];
    const int*   sources = (const int*)d_in[19];
    const int*   targets = (const int*)d_in[20];
    float* out = (float*)d_out;

    float *px, *pqkv;
    bf16 *pasp, *pffsp, *pwqkv, *pwproj, *pwf1, *pwf2, *pwlm;
    cudaGetSymbolAddress((void**)&px,    g_x);
    cudaGetSymbolAddress((void**)&pqkv,  g_qkv);
    cudaGetSymbolAddress((void**)&pasp,  g_asp);
    cudaGetSymbolAddress((void**)&pffsp, g_ffsp);
    cudaGetSymbolAddress((void**)&pwqkv, g_wqkvB);
    cudaGetSymbolAddress((void**)&pwproj,g_wprojB);
    cudaGetSymbolAddress((void**)&pwf1,  g_wf1B);
    cudaGetSymbolAddress((void**)&pwf2,  g_wf2B);
    cudaGetSymbolAddress((void**)&pwlm,  g_wlmB);

    // ---- pack weights (split + transpose) ----
    dim3 tb32(32, 8);
    qkvpack_kernel<<<dim3(2, 24, 108), tb32>>>(wq, wk, wv);
    for (int i = 0; i < NB; i++) {
        tsplit_kernel<<<dim3(24, 24),  tb32>>>(wproj + (size_t)i*768*768,  pwproj + (size_t)i*768*2304,  768, 768);
        tsplit_kernel<<<dim3(288, 24), tb32>>>(wf1   + (size_t)i*768*9216, pwf1   + (size_t)i*9216*2304, 768, 9216);
        tsplit_kernel<<<dim3(24, 288), tb32>>>(wf2   + (size_t)i*9216*768, pwf2   + (size_t)i*768*27648, 9216, 768);
    }
    tsplit_kernel<<<dim3(1000, 24), tb32>>>(wlm, pwlm, 768, Vv);

    embed_kernel<<<(Mrows * Cc + 255) / 256, 256>>>(tok_emb, pos_emb, sources);

    for (int i = 0; i < NB; i++) {
        ln_kernel<<<Mrows, 256>>>(px, g1 + i * Cc, b1 + i * Cc);
        hmma_gemm<0><<<dim3(32, 18), 256>>>(
            pasp, pwqkv + (size_t)i*2304*2304, nullptr, nullptr, pqkv, nullptr, 2304, QKVN, 0);
        attn_kernel<<<dim3(NBATCH * Hh, Tt / 64), 256>>>(pqkv);
        hmma_gemm<2><<<dim3(32, 6), 256>>>(
            pasp, pwproj + (size_t)i*768*2304, bproj + i * Cc, px, px, nullptr, 2304, Cc, 0);
        ln_kernel<<<Mrows, 256>>>(px, g2 + i * Cc, b2 + i * Cc);
        hmma_gemm<1><<<dim3(32, 72), 256>>>(
            pasp, pwf1 + (size_t)i*9216*2304, bf1 + i * FFf, nullptr, nullptr, pffsp, 2304, FFf, FFf);
        hmma_gemm<2><<<dim3(32, 6), 256>>>(
            pffsp, pwf2 + (size_t)i*768*27648, bf2 + i * Cc, px, px, nullptr, 27648, Cc, 0);
    }

    ln_kernel<<<Mrows, 256>>>(px, gf, bfv);
    hmma_gemm<0><<<dim3(32, 250), 256>>>(
        pasp, pwlm, blm, nullptr, out, nullptr, 2304, Vv, 0);

    loss_rows_kernel<<<Mrows, 256>>>(out, targets);
    loss_reduce_kernel<<<1, 256>>>(out, (long long)out_size);
}

// round 11
// speedup vs baseline: 1.8262x; 1.1550x over previous
#include <cuda_runtime.h>
#include <cuda_bf16.h>
#include <math.h>
#include <stdint.h>

#define Vv    32000
#define Cc    768
#define Tt    1024
#define Hh    12
#define FFf   9216
#define NB    3
#define Mrows 4096
#define QKVN  2304
#define NBATCH 4
#define LOGITS_N 131072000LL
#define ATT_SCALE 0.036084391824351615f

typedef __nv_bfloat16 bf16;

// ---- scratch (device globals; no runtime allocation) ----
__device__ float g_x   [Mrows*Cc];
__device__ float g_qkv [Mrows*QKVN];
__device__ __align__(128) bf16 g_asp [(size_t)Mrows*2304];        // split activations [M, 3*768] = [hi|lo|hi]
__device__ __align__(128) bf16 g_ffsp[(size_t)Mrows*27648];       // split FF activations [M, 3*9216]
__device__ float g_rowloss[Mrows];
// split, transposed weights: [N, 3K] bf16, K-major, [hi | hi | lo]
__device__ __align__(128) bf16 g_wqkvB [(size_t)NB*2304*2304];
__device__ __align__(128) bf16 g_wprojB[(size_t)NB*768*2304];
__device__ __align__(128) bf16 g_wf1B  [(size_t)NB*9216*2304];
__device__ __align__(128) bf16 g_wf2B  [(size_t)NB*768*27648];
__device__ __align__(128) bf16 g_wlmB  [(size_t)Vv*2304];

// ================= PTX helpers (arch-portable, sm_80+) =================
__device__ __forceinline__ uint32_t smem_u32(const void* p) {
    uint32_t a;
    asm("{ .reg .u64 t; cvta.to.shared.u64 t, %1; cvt.u32.u64 %0, t; }" : "=r"(a) : "l"(p));
    return a;
}
#define CP16(dst, src)  asm volatile("cp.async.cg.shared.global [%0], [%1], 16;" :: "r"(dst), "l"(src))
#define CP_COMMIT()     asm volatile("cp.async.commit_group;" ::: "memory")
#define CP_WAITG(n)     asm volatile("cp.async.wait_group %0;" :: "n"(n) : "memory")

__device__ __forceinline__ void ldm_x4(uint32_t* r, uint32_t addr) {
    asm volatile("ldmatrix.sync.aligned.m8n8.x4.shared.b16 {%0,%1,%2,%3}, [%4];"
        : "=r"(r[0]), "=r"(r[1]), "=r"(r[2]), "=r"(r[3]) : "r"(addr));
}
__device__ __forceinline__ void mma16816(float* c, const uint32_t* a, const uint32_t* b) {
    asm volatile("mma.sync.aligned.m16n8k16.row.col.f32.bf16.bf16.f32 "
        "{%0,%1,%2,%3}, {%4,%5,%6,%7}, {%8,%9}, {%0,%1,%2,%3};"
        : "+f"(c[0]), "+f"(c[1]), "+f"(c[2]), "+f"(c[3])
        : "r"(a[0]), "r"(a[1]), "r"(a[2]), "r"(a[3]), "r"(b[0]), "r"(b[1]));
}

__device__ __forceinline__ void split_store(bf16* p, size_t o, size_t K, float v) {
    bf16 h = __float2bfloat16(v);
    bf16 l = __float2bfloat16(v - __bfloat162float(h));
    p[o] = h; p[o + K] = l; p[o + 2*K] = h;   // A layout: [hi | lo | hi]
}

// ================= HMMA GEMM =================
// C[M,N] = A'[M,K3] @ B'[N,K3]^T  (bf16, fp32 accum)
// Tile 128x128, BK=32, 256 threads, 8 warps (4 m x 2 n), warp tile 32x64.
// 3-stage cp.async pipeline, ONE __syncthreads per iteration, 2 CTAs/SM.
// MODE 0: outF = acc (+bias)        MODE 1: relu(acc+bias) -> split bf16 outS
// MODE 2: outF = acc + bias + res
#define SSTR 40   // smem row stride in bf16 (80B): conflict-free ldmatrix
#define NSTG 3
template<int MODE>
__global__ void __launch_bounds__(256, 2)
hmma_gemm(const bf16* __restrict__ A, const bf16* __restrict__ Bw,
          const float* __restrict__ bias, const float* __restrict__ res,
          float* __restrict__ outF, bf16* __restrict__ outS,
          int K3, int N, int KoutS)
{
    __shared__ __align__(16) bf16 As[NSTG][128 * SSTR];
    __shared__ __align__(16) bf16 Bs[NSTG][128 * SSTR];

    int tid = threadIdx.x, lane = tid & 31, wid = tid >> 5;
    int warp_m = wid & 3, warp_n = wid >> 2;       // 4 x 2 warps
    int gm = blockIdx.x, gn = blockIdx.y;

    const bf16* Aptr = A  + (size_t)(gm * 128) * K3;
    const bf16* Bptr = Bw + (size_t)(gn * 128) * K3;

    float acc[2][8][4];
#pragma unroll
    for (int i = 0; i < 2; i++)
#pragma unroll
        for (int j = 0; j < 8; j++)
#pragma unroll
            for (int q = 0; q < 4; q++) acc[i][j][q] = 0.f;

    int r0 = tid >> 2, sub = (tid & 3) * 8;        // cp.async row / elem-offset

    auto load_tiles = [&](int stage, int k0) {
        uint32_t sa = smem_u32(&As[stage][0]);
        uint32_t sb = smem_u32(&Bs[stage][0]);
#pragma unroll
        for (int hf = 0; hf < 2; hf++) {
            int row = r0 + hf * 64;
            CP16(sa + (row * SSTR + sub) * 2, Aptr + (size_t)row * K3 + k0 + sub);
            CP16(sb + (row * SSTR + sub) * 2, Bptr + (size_t)row * K3 + k0 + sub);
        }
        CP_COMMIT();
    };

    int NK = K3 / 32;
    load_tiles(0, 0);
    load_tiles(1, 32);

    for (int it = 0; it < NK; it++) {
        CP_WAITG(1);           // stage it resident (in-order groups; <=1 pending)
        __syncthreads();       // visibility of stage it + safe overwrite of stage it-1

        int nx = it + NSTG - 1;
        if (nx < NK) load_tiles(nx % NSTG, nx * 32);

        int st = it % NSTG;
        uint32_t abase = smem_u32(&As[st][0]);
        uint32_t bbase = smem_u32(&Bs[st][0]);
#pragma unroll
        for (int kk = 0; kk < 32; kk += 16) {
            uint32_t af[2][4], bfr[4][4];
#pragma unroll
            for (int mt = 0; mt < 2; mt++) {
                int row = warp_m * 32 + mt * 16 + (lane & 15);
                int col = kk + (lane >> 4) * 8;
                ldm_x4(af[mt], abase + (row * SSTR + col) * 2);
            }
#pragma unroll
            for (int bt = 0; bt < 4; bt++) {
                int row = warp_n * 64 + bt * 16 + (lane & 15);
                int col = kk + (lane >> 4) * 8;
                ldm_x4(bfr[bt], bbase + (row * SSTR + col) * 2);
            }
#pragma unroll
            for (int mt = 0; mt < 2; mt++)
#pragma unroll
                for (int bt = 0; bt < 4; bt++) {
                    uint32_t blo[2] = { bfr[bt][0], bfr[bt][2] };  // n = bt*16+0..7
                    uint32_t bhi[2] = { bfr[bt][1], bfr[bt][3] };  // n = bt*16+8..15
                    mma16816(acc[mt][bt * 2 + 0], af[mt], blo);
                    mma16816(acc[mt][bt * 2 + 1], af[mt], bhi);
                }
        }
    }

    // epilogue: c fragment rows lane>>2 (+8), cols (lane&3)*2 (+1)
    int rbase = gm * 128 + warp_m * 32;
    int cbase = gn * 128 + warp_n * 64;
#pragma unroll
    for (int mt = 0; mt < 2; mt++) {
#pragma unroll
        for (int nt = 0; nt < 8; nt++) {
#pragma unroll
            for (int hf = 0; hf < 2; hf++) {
                int grow = rbase + mt * 16 + (lane >> 2) + hf * 8;
                int gcol = cbase + nt * 8 + (lane & 3) * 2;
                float v0 = acc[mt][nt][hf * 2 + 0];
                float v1 = acc[mt][nt][hf * 2 + 1];
                if (bias) { v0 += bias[gcol]; v1 += bias[gcol + 1]; }
                if (MODE == 2) {
                    const float* rr = res + (size_t)grow * N + gcol;
                    v0 += rr[0]; v1 += rr[1];
                }
                if (MODE == 1) {
                    v0 = fmaxf(v0, 0.f); v1 = fmaxf(v1, 0.f);
                    size_t o = (size_t)grow * (3 * (size_t)KoutS) + gcol;
                    split_store(outS, o,     KoutS, v0);
                    split_store(outS, o + 1, KoutS, v1);
                } else {
                    float* po = outF + (size_t)grow * N + gcol;
                    po[0] = v0; po[1] = v1;
                }
            }
        }
    }
}

// ================= weight packing =================
// src [K,N] fp32 -> dst [N,3K] bf16 K-major: [hi | hi | lo]
__global__ void tsplit_kernel(const float* __restrict__ src, bf16* __restrict__ dst,
                              int K, int N) {
    __shared__ float t[32][33];
    int n0 = blockIdx.x * 32, k0 = blockIdx.y * 32;
    int tx = threadIdx.x, ty = threadIdx.y;
#pragma unroll
    for (int i = 0; i < 32; i += 8) t[ty + i][tx] = src[(size_t)(k0 + ty + i) * N + n0 + tx];
    __syncthreads();
#pragma unroll
    for (int i = 0; i < 32; i += 8) {
        float v = t[tx][ty + i];
        int n = n0 + ty + i, k = k0 + tx;
        bf16 h = __float2bfloat16(v);
        bf16 l = __float2bfloat16(v - __bfloat162float(h));
        size_t o = (size_t)n * (3 * (size_t)K) + k;
        dst[o] = h; dst[o + K] = h; dst[o + 2 * K] = l;
    }
}

// wq/wk/wv [blk][H][768][64] -> g_wqkvB [blk][N=2304][3K=2304]
__global__ void qkvpack_kernel(const float* __restrict__ wq, const float* __restrict__ wk,
                               const float* __restrict__ wv) {
    __shared__ float t[32][33];
    int z = blockIdx.z;
    int blk = z / 36, rem = z % 36, mat = rem / 12, h = rem % 12;
    const float* src = (mat == 0 ? wq : mat == 1 ? wk : wv) + (size_t)(blk * 12 + h) * 768 * 64;
    int d0 = blockIdx.x * 32, c0 = blockIdx.y * 32;
    int tx = threadIdx.x, ty = threadIdx.y;
#pragma unroll
    for (int i = 0; i < 32; i += 8) t[ty + i][tx] = src[(size_t)(c0 + ty + i) * 64 + d0 + tx];
    __syncthreads();
    bf16* dst = g_wqkvB + (size_t)blk * 2304 * 2304;
#pragma unroll
    for (int i = 0; i < 32; i += 8) {
        float v = t[tx][ty + i];
        int n = mat * 768 + h * 64 + d0 + ty + i;
        int c = c0 + tx;
        bf16 hh = __float2bfloat16(v);
        bf16 ll = __float2bfloat16(v - __bfloat162float(hh));
        size_t o = (size_t)n * 2304 + c;
        dst[o] = hh; dst[o + 768] = hh; dst[o + 1536] = ll;
    }
}

// ================= embed =================
__global__ void embed_kernel(const float* __restrict__ tok, const float* __restrict__ pos,
                             const int* __restrict__ src) {
    int idx = blockIdx.x * blockDim.x + threadIdx.x;
    if (idx >= Mrows * Cc) return;
    int r = idx / Cc, c = idx % Cc;
    g_x[idx] = tok[(size_t)src[r] * Cc + c] + pos[(size_t)(r % Tt) * Cc + c];
}

// ================= LayerNorm -> split bf16 =================
__global__ void ln_kernel(const float* __restrict__ x, const float* __restrict__ g,
                          const float* __restrict__ b) {
    int r = blockIdx.x, tid = threadIdx.x;
    const float* xr = x + (size_t)r * Cc;
    float vals[3];
    float s = 0.f, ss = 0.f;
#pragma unroll
    for (int i = 0; i < 3; i++) {
        float v = xr[tid + i * 256];
        vals[i] = v; s += v; ss += v * v;
    }
#pragma unroll
    for (int o = 16; o; o >>= 1) {
        s  += __shfl_xor_sync(0xffffffffu, s,  o);
        ss += __shfl_xor_sync(0xffffffffu, ss, o);
    }
    __shared__ float sh_s[8], sh_ss[8], smean, srstd;
    int w = tid >> 5, l = tid & 31;
    if (l == 0) { sh_s[w] = s; sh_ss[w] = ss; }
    __syncthreads();
    if (tid == 0) {
        float S = 0.f, SS = 0.f;
        for (int i = 0; i < 8; i++) { S += sh_s[i]; SS += sh_ss[i]; }
        float m = S / Cc;
        smean = m; srstd = rsqrtf(SS / Cc - m * m + 1e-5f);
    }
    __syncthreads();
    float m = smean, rstd = srstd;
#pragma unroll
    for (int i = 0; i < 3; i++) {
        int c = tid + i * 256;
        float y = (vals[i] - m) * rstd * g[c] + b[c];
        split_store(g_asp, (size_t)r * 2304 + c, 768, y);
    }
}

// ================= causal attention (fp32), split output =================
__global__ void __launch_bounds__(256)
attn_kernel(const float* __restrict__ QKV) {
    int bh = blockIdx.x;
    int b = bh / Hh, h = bh % Hh;
    int qt0 = blockIdx.y * 64;
    int tid = threadIdx.x;

    __shared__ float Qs[64][64];
    __shared__ float Ks[32][65];
    __shared__ float Vs[32][65];
    __shared__ float Ps[64][33];
    __shared__ float mrow[64], lrow[64], arow_s[64];

#pragma unroll
    for (int i = 0; i < 16; i++) {
        int e = tid + i * 256;
        int r = e >> 6, d = e & 63;
        Qs[r][d] = QKV[((size_t)(b * Tt + qt0 + r)) * QKVN + h * 64 + d];
    }
    if (tid < 64) { mrow[tid] = -1e30f; lrow[tid] = 0.f; }

    float o[16];
#pragma unroll
    for (int i = 0; i < 16; i++) o[i] = 0.f;

    int d_o = tid & 63, rg_o = tid >> 6;
    int s_s = tid & 31, rg_s = tid >> 5;

    int nkt = (qt0 + 64) / 32;
    for (int kt = 0; kt < nkt; kt++) {
        __syncthreads();
#pragma unroll
        for (int i = 0; i < 8; i++) {
            int e = tid + i * 256;
            int s = e >> 6, d = e & 63;
            size_t gi = ((size_t)(b * Tt + kt * 32 + s)) * QKVN + h * 64 + d;
            Ks[s][d] = QKV[gi + 768];
            Vs[s][d] = QKV[gi + 1536];
        }
        __syncthreads();
#pragma unroll
        for (int i = 0; i < 8; i++) {
            int r = rg_s * 8 + i;
            float a = 0.f;
#pragma unroll
            for (int k = 0; k < 64; k++) a += Qs[r][k] * Ks[s_s][k];
            int sg = kt * 32 + s_s, tg = qt0 + r;
            Ps[r][s_s] = (sg <= tg) ? a * ATT_SCALE : -1e30f;
        }
        __syncthreads();
        if (tid < 64) {
            int r = tid;
            float m_old = mrow[r], mx = m_old;
#pragma unroll
            for (int s = 0; s < 32; s++) mx = fmaxf(mx, Ps[r][s]);
            float alpha = expf(m_old - mx), sum = 0.f;
#pragma unroll
            for (int s = 0; s < 32; s++) { float p = expf(Ps[r][s] - mx); Ps[r][s] = p; sum += p; }
            mrow[r] = mx; lrow[r] = lrow[r] * alpha + sum; arow_s[r] = alpha;
        }
        __syncthreads();
#pragma unroll
        for (int i = 0; i < 16; i++) {
            int r = rg_o * 16 + i;
            float al = arow_s[r], a = 0.f;
#pragma unroll
            for (int s = 0; s < 32; s++) a += Ps[r][s] * Vs[s][d_o];
            o[i] = o[i] * al + a;
        }
    }
#pragma unroll
    for (int i = 0; i < 16; i++) {
        int r = rg_o * 16 + i;
        float v = o[i] / lrow[r];
        split_store(g_asp, ((size_t)(b * Tt + qt0 + r)) * 2304 + h * 64 + d_o, 768, v);
    }
}

// ================= loss (one-pass online softmax) =================
__global__ void loss_rows_kernel(const float* __restrict__ logits, const int* __restrict__ targets) {
    int r = blockIdx.x, tid = threadIdx.x;
    const float* row = logits + (size_t)r * Vv;
    float mx = -1e30f, s = 0.f;
    for (int c = tid; c < Vv; c += 256) {
        float v = row[c];
        if (v > mx) { s = s * expf(mx - v) + 1.f; mx = v; }
        else        { s += expf(v - mx); }
    }
#pragma unroll
    for (int o = 16; o; o >>= 1) {
        float mo = __shfl_xor_sync(0xffffffffu, mx, o);
        float so = __shfl_xor_sync(0xffffffffu, s,  o);
        float M = fmaxf(mx, mo);
        s = s * expf(mx - M) + so * expf(mo - M);
        mx = M;
    }
    __shared__ float shm[8], shs[8];
    int w = tid >> 5;
    if ((tid & 31) == 0) { shm[w] = mx; shs[w] = s; }
    __syncthreads();
    if (tid == 0) {
        float M = shm[0];
        for (int i = 1; i < 8; i++) M = fmaxf(M, shm[i]);
        float S = 0.f;
        for (int i = 0; i < 8; i++) S += shs[i] * expf(shm[i] - M);
        g_rowloss[r] = M + logf(S) - row[targets[r]];
    }
}

__global__ void loss_reduce_kernel(float* __restrict__ d_out, long long out_size) {
    int tid = threadIdx.x;
    __shared__ float sh[8];
    float s = 0.f;
    for (int i = tid; i < Mrows; i += 256) s += g_rowloss[i];
#pragma unroll
    for (int o = 16; o; o >>= 1) s += __shfl_xor_sync(0xffffffffu, s, o);
    if ((tid & 31) == 0) sh[tid >> 5] = s;
    __syncthreads();
    if (tid == 0) {
        float S = 0.f;
        for (int i = 0; i < 8; i++) S += sh[i];
        float loss = S / (float)Mrows;
        for (long long i = LOGITS_N; i < out_size; i++) d_out[i] = loss;
    }
}

// ================= host orchestration =================
extern "C" void kernel_launch(void* const* d_in, const int* in_sizes, int n_in,
                              void* d_out, int out_size) {
    const float* tok_emb = (const float*)d_in[0];
    const float* pos_emb = (const float*)d_in[1];
    const float* wq      = (const float*)d_in[2];
    const float* wk      = (const float*)d_in[3];
    const float* wv      = (const float*)d_in[4];
    const float* wproj   = (const float*)d_in[5];
    const float* bproj   = (const float*)d_in[6];
    const float* g1      = (const float*)d_in[7];
    const float* b1      = (const float*)d_in[8];
    const float* g2      = (const float*)d_in[9];
    const float* b2      = (const float*)d_in[10];
    const float* wf1     = (const float*)d_in[11];
    const float* bf1     = (const float*)d_in[12];
    const float* wf2     = (const float*)d_in[13];
    const float* bf2     = (const float*)d_in[14];
    const float* gf      = (const float*)d_in[15];
    const float* bfv     = (const float*)d_in[16];
    const float* wlm     = (const float*)d_in[17];
    const float* blm     = (const float*)d_in[18];
    const int*   sources = (const int*)d_in[19];
    const int*   targets = (const int*)d_in[20];
    float* out = (float*)d_out;

    float *px, *pqkv;
    bf16 *pasp, *pffsp, *pwqkv, *pwproj, *pwf1, *pwf2, *pwlm;
    cudaGetSymbolAddress((void**)&px,    g_x);
    cudaGetSymbolAddress((void**)&pqkv,  g_qkv);
    cudaGetSymbolAddress((void**)&pasp,  g_asp);
    cudaGetSymbolAddress((void**)&pffsp, g_ffsp);
    cudaGetSymbolAddress((void**)&pwqkv, g_wqkvB);
    cudaGetSymbolAddress((void**)&pwproj,g_wprojB);
    cudaGetSymbolAddress((void**)&pwf1,  g_wf1B);
    cudaGetSymbolAddress((void**)&pwf2,  g_wf2B);
    cudaGetSymbolAddress((void**)&pwlm,  g_wlmB);

    // ---- pack weights (split + transpose) ----
    dim3 tb32(32, 8);
    qkvpack_kernel<<<dim3(2, 24, 108), tb32>>>(wq, wk, wv);
    for (int i = 0; i < NB; i++) {
        tsplit_kernel<<<dim3(24, 24),  tb32>>>(wproj + (size_t)i*768*768,  pwproj + (size_t)i*768*2304,  768, 768);
        tsplit_kernel<<<dim3(288, 24), tb32>>>(wf1   + (size_t)i*768*9216, pwf1   + (size_t)i*9216*2304, 768, 9216);
        tsplit_kernel<<<dim3(24, 288), tb32>>>(wf2   + (size_t)i*9216*768, pwf2   + (size_t)i*768*27648, 9216, 768);
    }
    tsplit_kernel<<<dim3(1000, 24), tb32>>>(wlm, pwlm, 768, Vv);

    embed_kernel<<<(Mrows * Cc + 255) / 256, 256>>>(tok_emb, pos_emb, sources);

    for (int i = 0; i < NB; i++) {
        ln_kernel<<<Mrows, 256>>>(px, g1 + i * Cc, b1 + i * Cc);
        hmma_gemm<0><<<dim3(32, 18), 256>>>(
            pasp, pwqkv + (size_t)i*2304*2304, nullptr, nullptr, pqkv, nullptr, 2304, QKVN, 0);
        attn_kernel<<<dim3(NBATCH * Hh, Tt / 64), 256>>>(pqkv);
        hmma_gemm<2><<<dim3(32, 6), 256>>>(
            pasp, pwproj + (size_t)i*768*2304, bproj + i * Cc, px, px, nullptr, 2304, Cc, 0);
        ln_kernel<<<Mrows, 256>>>(px, g2 + i * Cc, b2 + i * Cc);
        hmma_gemm<1><<<dim3(32, 72), 256>>>(
            pasp, pwf1 + (size_t)i*9216*2304, bf1 + i * FFf, nullptr, nullptr, pffsp, 2304, FFf, FFf);
        hmma_gemm<2><<<dim3(32, 6), 256>>>(
            pffsp, pwf2 + (size_t)i*768*27648, bf2 + i * Cc, px, px, nullptr, 27648, Cc, 0);
    }

    ln_kernel<<<Mrows, 256>>>(px, gf, bfv);
    hmma_gemm<0><<<dim3(32, 250), 256>>>(
        pasp, pwlm, blm, nullptr, out, nullptr, 2304, Vv, 0);

    loss_rows_kernel<<<Mrows, 256>>>(out, targets);
    loss_reduce_kernel<<<1, 256>>>(out, (long long)out_size);
}